// round 14
// baseline (speedup 1.0000x reference)
#include <cuda_runtime.h>

#define SEQ_LEN   8192
#define STATE_LEN 4096
#define T_DIM     1024
#define THREADS   512
#define SWEEPS    2                    // 2 sweeps x 8 floats x 512 threads = 8192 cols
#define SPLIT     2                    // CTAs per distinct t
#define SCAN_LEN  (STATE_LEN / SPLIT)  // 2048 cur entries scanned per CTA
#define GRID_MAIN (T_DIM * SPLIT)      // 2048

// Plain 256-bit store (sm_100+). No cache hint — R12 showed evict_last thrashes.
__device__ __forceinline__ void st256(float* p, const float* v)
{
    asm volatile(
        "st.global.v8.b32 [%0], {%1, %2, %3, %4, %5, %6, %7, %8};"
        :: "l"(p),
           "f"(v[0]), "f"(v[1]), "f"(v[2]), "f"(v[3]),
           "f"(v[4]), "f"(v[5]), "f"(v[6]), "f"(v[7])
        : "memory");
}

__global__ __launch_bounds__(THREADS)
void attn_time_onelaunch_kernel(const int* __restrict__ his,
                                const int* __restrict__ cur,
                                const float* __restrict__ tsm,
                                float* __restrict__ out)
{
    __shared__ float w[T_DIM];            // exp(row), 4 KB
    __shared__ float red[THREADS / 32];
    __shared__ int   match[SCAN_LEN];     // worst-case safe (8 KB)
    __shared__ int   mcnt;

    const int tid  = threadIdx.x;
    const int t    = blockIdx.x >> 1;
    const int half = blockIdx.x & 1;

    if (tid == 0) mcnt = 0;
    __syncthreads();

    // ---- scan this CTA's half of cur for rows using t (int4, L2-resident) ----
    {
        const int4* cur4 = reinterpret_cast<const int4*>(cur + half * SCAN_LEN);
        int4 c = cur4[tid];                         // 512 * 4 = 2048 entries
        int base = half * SCAN_LEN + tid * 4;
        if (c.x == t) match[atomicAdd(&mcnt, 1)] = base + 0;
        if (c.y == t) match[atomicAdd(&mcnt, 1)] = base + 1;
        if (c.z == t) match[atomicAdd(&mcnt, 1)] = base + 2;
        if (c.w == t) match[atomicAdd(&mcnt, 1)] = base + 3;
    }
    __syncthreads();
    const int cnt = mcnt;
    if (cnt == 0) return;                           // nobody uses this t-half

    // ---- exp weights for row t (no max shift: inputs ~N(0,1), exp range safe) ----
    {
        const float2* src = reinterpret_cast<const float2*>(tsm + (size_t)t * T_DIM);
        float2 rv = src[tid];
        float2 ev;
        ev.x = __expf(rv.x);
        ev.y = __expf(rv.y);
        reinterpret_cast<float2*>(w)[tid] = ev;
    }
    __syncthreads();

    // ---- gather once into registers (8 consecutive cols per thread per sweep) ----
    float e[SWEEPS * 8];
    float s = 0.0f;
    const int4* his4 = reinterpret_cast<const int4*>(his);
    #pragma unroll
    for (int sw = 0; sw < SWEEPS; sw++) {
        int idx = sw * THREADS + tid;               // owns cols [idx*8, idx*8+8)
        int4 h0 = his4[idx * 2 + 0];
        int4 h1 = his4[idx * 2 + 1];
        float a0 = w[h0.x], a1 = w[h0.y], a2 = w[h0.z], a3 = w[h0.w];
        float a4 = w[h1.x], a5 = w[h1.y], a6 = w[h1.z], a7 = w[h1.w];
        e[sw * 8 + 0] = a0; e[sw * 8 + 1] = a1;
        e[sw * 8 + 2] = a2; e[sw * 8 + 3] = a3;
        e[sw * 8 + 4] = a4; e[sw * 8 + 5] = a5;
        e[sw * 8 + 6] = a6; e[sw * 8 + 7] = a7;
        s += ((a0 + a1) + (a2 + a3)) + ((a4 + a5) + (a6 + a7));
    }

    // ---- block sum ----
    #pragma unroll
    for (int off = 16; off; off >>= 1)
        s += __shfl_xor_sync(0xffffffff, s, off);
    if ((tid & 31) == 0) red[tid >> 5] = s;
    __syncthreads();
    float bs = 0.0f;
    #pragma unroll
    for (int k = 0; k < THREADS / 32; k++) bs += red[k];
    const float inv = 1.0f / bs;

    // ---- normalize once in registers ----
    #pragma unroll
    for (int k = 0; k < SWEEPS * 8; k++) e[k] *= inv;

    // ---- store to every matched row: 256-bit STG (half the LSU issue slots) ----
    #pragma unroll
    for (int sw = 0; sw < SWEEPS; sw++) {
        int idx = sw * THREADS + tid;
        for (int r = 0; r < cnt; r++) {
            float* o = out + (size_t)match[r] * SEQ_LEN;
            st256(o + idx * 8, &e[sw * 8]);
        }
    }
}

extern "C" void kernel_launch(void* const* d_in, const int* in_sizes, int n_in,
                              void* d_out, int out_size)
{
    const int*   his = (const int*)d_in[0];    // [8192] int32
    const int*   cur = (const int*)d_in[1];    // [4096] int32
    const float* tsm = (const float*)d_in[2];  // [1024*1024] fp32
    float*       out = (float*)d_out;          // [4096*8192] fp32

    attn_time_onelaunch_kernel<<<GRID_MAIN, THREADS>>>(his, cur, tsm, out);
}

// round 15
// speedup vs baseline: 1.0749x; 1.0749x over previous
#include <cuda_runtime.h>

#define SEQ_LEN   8192
#define STATE_LEN 4096
#define T_DIM     1024
#define THREADS   512
#define ITERS     4                    // 4 iters x float4 x 512 threads = 8192 cols
#define SPLIT     2                    // CTAs per distinct t
#define SCAN_LEN  (STATE_LEN / SPLIT)  // 2048 cur entries scanned per CTA
#define GRID_MAIN (T_DIM * SPLIT)      // 2048

__global__ __launch_bounds__(THREADS)
void attn_time_onelaunch_kernel(const int* __restrict__ his,
                                const int* __restrict__ cur,
                                const float* __restrict__ tsm,
                                float* __restrict__ out)
{
    __shared__ float w[T_DIM];            // exp(row), 4 KB
    __shared__ float red[THREADS / 32];
    __shared__ int   match[SCAN_LEN];     // worst-case safe (8 KB)
    __shared__ int   mcnt;

    const int tid  = threadIdx.x;
    const int t    = blockIdx.x >> 1;
    const int half = blockIdx.x & 1;

    if (tid == 0) mcnt = 0;
    __syncthreads();

    // ---- scan this CTA's half of cur for rows using t (int4, L2-resident) ----
    {
        const int4* cur4 = reinterpret_cast<const int4*>(cur + half * SCAN_LEN);
        int4 c = cur4[tid];                         // 512 * 4 = 2048 entries
        int base = half * SCAN_LEN + tid * 4;
        if (c.x == t) match[atomicAdd(&mcnt, 1)] = base + 0;
        if (c.y == t) match[atomicAdd(&mcnt, 1)] = base + 1;
        if (c.z == t) match[atomicAdd(&mcnt, 1)] = base + 2;
        if (c.w == t) match[atomicAdd(&mcnt, 1)] = base + 3;
    }
    __syncthreads();
    const int cnt = mcnt;
    if (cnt == 0) return;                           // nobody uses this t-half

    // ---- exp weights for row t (no max shift: inputs ~N(0,1), exp range safe) ----
    {
        const float2* src = reinterpret_cast<const float2*>(tsm + (size_t)t * T_DIM);
        float2 rv = src[tid];
        float2 ev;
        ev.x = __expf(rv.x);
        ev.y = __expf(rv.y);
        reinterpret_cast<float2*>(w)[tid] = ev;
    }
    __syncthreads();

    // ---- gather once into registers, thread-local sum ----
    float e[ITERS * 4];
    float s = 0.0f;
    const int4* his4 = reinterpret_cast<const int4*>(his);
    #pragma unroll
    for (int it = 0; it < ITERS; it++) {
        int4 h = his4[it * THREADS + tid];
        float a = w[h.x];
        float b = w[h.y];
        float g = w[h.z];
        float d = w[h.w];
        e[it * 4 + 0] = a;
        e[it * 4 + 1] = b;
        e[it * 4 + 2] = g;
        e[it * 4 + 3] = d;
        s += (a + b) + (g + d);
    }

    // ---- block sum ----
    #pragma unroll
    for (int off = 16; off; off >>= 1)
        s += __shfl_xor_sync(0xffffffff, s, off);
    if ((tid & 31) == 0) red[tid >> 5] = s;
    __syncthreads();
    float bs = 0.0f;
    #pragma unroll
    for (int k = 0; k < THREADS / 32; k++) bs += red[k];
    const float inv = 1.0f / bs;

    // ---- normalize once in registers ----
    #pragma unroll
    for (int k = 0; k < ITERS * 4; k++) e[k] *= inv;

    // ---- store: r-outer / it-inner so each 32 KB row is one contiguous burst ----
    for (int r = 0; r < cnt; r++) {
        float4* o = reinterpret_cast<float4*>(out + (size_t)match[r] * SEQ_LEN);
        #pragma unroll
        for (int it = 0; it < ITERS; it++) {
            float4 v;
            v.x = e[it * 4 + 0];
            v.y = e[it * 4 + 1];
            v.z = e[it * 4 + 2];
            v.w = e[it * 4 + 3];
            __stcs(&o[it * THREADS + tid], v);
        }
    }
}

extern "C" void kernel_launch(void* const* d_in, const int* in_sizes, int n_in,
                              void* d_out, int out_size)
{
    const int*   his = (const int*)d_in[0];    // [8192] int32
    const int*   cur = (const int*)d_in[1];    // [4096] int32
    const float* tsm = (const float*)d_in[2];  // [1024*1024] fp32
    float*       out = (float*)d_out;          // [4096*8192] fp32

    attn_time_onelaunch_kernel<<<GRID_MAIN, THREADS>>>(his, cur, tsm, out);
}

// round 16
// speedup vs baseline: 1.1379x; 1.0586x over previous
#include <cuda_runtime.h>

#define SEQ_LEN   8192
#define STATE_LEN 4096
#define T_DIM     1024
#define THREADS   512
#define ITERS     4                    // 4 iters x float4 x 512 threads = 8192 cols
#define SPLIT     2                    // CTAs per distinct t
#define SCAN_LEN  (STATE_LEN / SPLIT)  // 2048 cur entries scanned per CTA
#define GRID_MAIN (T_DIM * SPLIT)      // 2048

__global__ __launch_bounds__(THREADS)
void attn_time_onelaunch_kernel(const int* __restrict__ his,
                                const int* __restrict__ cur,
                                const float* __restrict__ tsm,
                                float* __restrict__ out)
{
    __shared__ float w[T_DIM];            // exp(row), 4 KB
    __shared__ float red[THREADS / 32];
    __shared__ int   match[SCAN_LEN];     // worst-case safe (8 KB)
    __shared__ int   mcnt;

    const int tid  = threadIdx.x;
    const int t    = blockIdx.x >> 1;
    const int half = blockIdx.x & 1;

    if (tid == 0) mcnt = 0;
    __syncthreads();

    // ---- issue tsm row load FIRST so its latency overlaps the cur scan ----
    const float2* tsrc = reinterpret_cast<const float2*>(tsm + (size_t)t * T_DIM);
    float2 rv = tsrc[tid];                          // in flight during scan

    // ---- scan this CTA's half of cur for rows using t (int4, L2-resident) ----
    {
        const int4* cur4 = reinterpret_cast<const int4*>(cur + half * SCAN_LEN);
        int4 c = cur4[tid];                         // 512 * 4 = 2048 entries
        int base = half * SCAN_LEN + tid * 4;
        if (c.x == t) match[atomicAdd(&mcnt, 1)] = base + 0;
        if (c.y == t) match[atomicAdd(&mcnt, 1)] = base + 1;
        if (c.z == t) match[atomicAdd(&mcnt, 1)] = base + 2;
        if (c.w == t) match[atomicAdd(&mcnt, 1)] = base + 3;
    }

    // ---- exp weights (no max shift: inputs ~N(0,1), __expf range-safe) ----
    {
        float2 ev;
        ev.x = __expf(rv.x);
        ev.y = __expf(rv.y);
        reinterpret_cast<float2*>(w)[tid] = ev;
    }

    // single barrier publishes BOTH match[]/mcnt and w[]
    __syncthreads();
    const int cnt = mcnt;
    if (cnt == 0) return;                           // nobody uses this t-half

    // ---- gather once into registers, thread-local sum ----
    float e[ITERS * 4];
    float s = 0.0f;
    const int4* his4 = reinterpret_cast<const int4*>(his);
    #pragma unroll
    for (int it = 0; it < ITERS; it++) {
        int4 h = his4[it * THREADS + tid];
        float a = w[h.x];
        float b = w[h.y];
        float g = w[h.z];
        float d = w[h.w];
        e[it * 4 + 0] = a;
        e[it * 4 + 1] = b;
        e[it * 4 + 2] = g;
        e[it * 4 + 3] = d;
        s += (a + b) + (g + d);
    }

    // ---- block sum ----
    #pragma unroll
    for (int off = 16; off; off >>= 1)
        s += __shfl_xor_sync(0xffffffff, s, off);
    if ((tid & 31) == 0) red[tid >> 5] = s;
    __syncthreads();
    float bs = 0.0f;
    #pragma unroll
    for (int k = 0; k < THREADS / 32; k++) bs += red[k];
    const float inv = 1.0f / bs;

    // ---- scale once, store to every matched row (it-outer / r-inner, R8 order) ----
    #pragma unroll
    for (int it = 0; it < ITERS; it++) {
        float4 v;
        v.x = e[it * 4 + 0] * inv;
        v.y = e[it * 4 + 1] * inv;
        v.z = e[it * 4 + 2] * inv;
        v.w = e[it * 4 + 3] * inv;
        for (int r = 0; r < cnt; r++) {
            float4* o = reinterpret_cast<float4*>(out + (size_t)match[r] * SEQ_LEN);
            __stcs(&o[it * THREADS + tid], v);
        }
    }
}

extern "C" void kernel_launch(void* const* d_in, const int* in_sizes, int n_in,
                              void* d_out, int out_size)
{
    const int*   his = (const int*)d_in[0];    // [8192] int32
    const int*   cur = (const int*)d_in[1];    // [4096] int32
    const float* tsm = (const float*)d_in[2];  // [1024*1024] fp32
    float*       out = (float*)d_out;          // [4096*8192] fp32

    attn_time_onelaunch_kernel<<<GRID_MAIN, THREADS>>>(his, cur, tsm, out);
}